// round 4
// baseline (speedup 1.0000x reference)
#include <cuda_runtime.h>
#include <cstdint>

#define T_STEPS 300
#define E_DIM   300
#define H_DIM   512
#define G_DIM   2048   // 4*H
#define N_EXP   13
#define V_SIZE  400000
#define NCTA    128    // recurrent CTAs; 4 hidden units each
#define ROWS_PER_BLK 32
#define SENTINEL 2.0f  // |h| <= 1.0 always, so 2.0f is unreachable

// Scratch (device globals: no allocation allowed)
__device__ float g_gates[T_STEPS * G_DIM];                      // input gates (+biases)
__device__ __align__(16) float g_h[(T_STEPS + 1) * H_DIM];      // step-indexed hidden states

// ---------------------------------------------------------------------------
// Volatile global access helpers (compiler cannot hoist/elide these)
// ---------------------------------------------------------------------------
__device__ __forceinline__ float2 ld_vol_f2(const float2* p) {
    float2 v;
    asm volatile("ld.volatile.global.v2.f32 {%0,%1}, [%2];"
                 : "=f"(v.x), "=f"(v.y) : "l"(p));
    return v;
}
__device__ __forceinline__ void st_vol_f(float* p, float v) {
    asm volatile("st.volatile.global.f32 [%0], %1;" :: "l"(p), "f"(v));
}

// ---------------------------------------------------------------------------
// Kernel 1: re-initialize h buffers each replay. g_h[0] = h0, rest = sentinel.
// ---------------------------------------------------------------------------
__global__ void init_kernel(const float* __restrict__ h0) {
    int idx = blockIdx.x * blockDim.x + threadIdx.x;
    if (idx < (T_STEPS + 1) * H_DIM)
        g_h[idx] = (idx < H_DIM) ? h0[idx] : SENTINEL;
}

// ---------------------------------------------------------------------------
// x-buffer layout probe: reference declares int64 but JAX w/o x64 yields int32.
// If truly int64, every odd 32-bit word is 0 (all ids in [0, 4e5)).
// ---------------------------------------------------------------------------
__device__ __forceinline__ bool probe_is_i64(const int* __restrict__ x32) {
    bool all_zero = true;
    #pragma unroll
    for (int i = 1; i < 64; i += 2) all_zero &= (x32[i] == 0);
    return all_zero;
}

__device__ __forceinline__ int load_token(const int* __restrict__ x32, int t, bool i64) {
    int v = i64 ? x32[2 * t] : x32[t];
    return (v < 0) ? 0 : (v >= V_SIZE ? V_SIZE - 1 : v);   // defensive clamp
}

// ---------------------------------------------------------------------------
// Kernel 2: input gates. Block = (expert, 32-row chunk). W_ih chunk in SMEM
// once; loop timesteps routed to this expert.
// gates[t][row] = dot(emb[x[t]], W_ih[e][row]) + b_ih[e][row] + b_hh[e][row]
// ---------------------------------------------------------------------------
__global__ void __launch_bounds__(256) gates_kernel(
    const int* __restrict__ x32, const int* __restrict__ tags,
    const float* __restrict__ emb, const float* __restrict__ W_ih,
    const float* __restrict__ b_ih, const float* __restrict__ b_hh)
{
    __shared__ float sw[ROWS_PER_BLK * E_DIM];   // 37.5 KB
    __shared__ float sx[E_DIM];
    __shared__ float sb[ROWS_PER_BLK];
    __shared__ int   stags[T_STEPS];
    __shared__ int   s_i64;

    const int e     = blockIdx.x / (G_DIM / ROWS_PER_BLK);
    const int chunk = blockIdx.x % (G_DIM / ROWS_PER_BLK);
    const int row0  = chunk * ROWS_PER_BLK;
    const int tid   = threadIdx.x;

    const float* wsrc = W_ih + ((size_t)e * G_DIM + row0) * E_DIM;
    for (int i = tid; i < ROWS_PER_BLK * E_DIM; i += 256) sw[i] = wsrc[i];
    if (tid < ROWS_PER_BLK)
        sb[tid] = b_ih[e * G_DIM + row0 + tid] + b_hh[e * G_DIM + row0 + tid];
    for (int i = tid; i < T_STEPS; i += 256) stags[i] = tags[i];
    if (tid == 0) s_i64 = probe_is_i64(x32) ? 1 : 0;
    __syncthreads();

    const bool i64  = (s_i64 != 0);
    const int row   = tid >> 3;   // 0..31
    const int lane8 = tid & 7;

    for (int t = 0; t < T_STEPS; t++) {
        if (stags[t] != e) continue;                 // uniform branch (smem)
        const float* xe = emb + (size_t)load_token(x32, t, i64) * E_DIM;
        for (int i = tid; i < E_DIM; i += 256) sx[i] = xe[i];
        __syncthreads();
        float acc = 0.f;
        for (int k = lane8; k < E_DIM; k += 8)
            acc += sw[row * E_DIM + k] * sx[k];
        #pragma unroll
        for (int off = 4; off; off >>= 1)
            acc += __shfl_down_sync(0xffffffffu, acc, off, 8);
        if (lane8 == 0)
            g_gates[t * G_DIM + row0 + row] = acc + sb[row];
        __syncthreads();
    }
}

// ---------------------------------------------------------------------------
// Kernel 3: persistent recurrent LSTM. 128 CTAs x 256 threads.
// CTA c owns hidden units [4c, 4c+4); 16 gate rows per step.
// Sync: sentinel polling (2.0f) on step-indexed g_h via volatile ld/st.
// ---------------------------------------------------------------------------
__device__ __forceinline__ float sigmoidf_(float v) { return 1.f / (1.f + expf(-v)); }

__global__ void __launch_bounds__(256, 1) lstm_kernel(
    const int* __restrict__ tags, const float* __restrict__ W_hh,
    const float* __restrict__ c0, float* __restrict__ d_out, int out_size)
{
    __shared__ float sh[H_DIM];       // h[s] staged for dot products
    __shared__ float ssum[16];        // per-row partial sums
    __shared__ float sgin[2][16];     // input gates (double-buffered)
    __shared__ int   stags[T_STEPS];

    const int tid    = threadIdx.x;
    const int base   = blockIdx.x * 4;        // first hidden unit owned
    const int rid    = tid >> 4;              // 0..15: gate row id
    const int lane16 = tid & 15;
    const int g      = rid >> 2;              // gate: 0=i 1=f 2=g 3=o
    const int ul     = rid & 3;               // unit within CTA
    const int row    = g * H_DIM + base + ul; // global gate row

    for (int i = tid; i < T_STEPS; i += 256) stags[i] = tags[i];
    float cval = 0.f, hval = 0.f;
    if (tid < 4) cval = c0[base + tid];
    __syncthreads();

    // Preload step-0 weights: thread handles k = lane16*4 + 64*m
    float4 wc[8], wn[8];
    {
        const float4* p = (const float4*)(W_hh + ((size_t)stags[0] * G_DIM + row) * H_DIM + lane16 * 4);
        #pragma unroll
        for (int m = 0; m < 8; m++) wc[m] = __ldg(&p[m * 16]);
    }

    const float2* ghp = (const float2*)g_h;

    for (int s = 0; s < T_STEPS; s++) {
        // 1. Prefetch next step's weights (tags known upfront -> hides L2 latency)
        {
            int sn = (s + 1 < T_STEPS) ? s + 1 : s;
            const float4* p = (const float4*)(W_hh + ((size_t)stags[sn] * G_DIM + row) * H_DIM + lane16 * 4);
            #pragma unroll
            for (int m = 0; m < 8; m++) wn[m] = __ldg(&p[m * 16]);
        }
        // 2. Prefetch this step's input gates (16 values per CTA)
        float gin = 0.f;
        if (tid < 16)
            gin = __ldg(&g_gates[s * G_DIM + (tid >> 2) * H_DIM + base + (tid & 3)]);

        // 3. Poll h[s]: each thread owns 2 floats; SENTINEL = not yet produced
        float2 hv = ld_vol_f2(&ghp[s * (H_DIM / 2) + tid]);
        while (hv.x == SENTINEL || hv.y == SENTINEL)
            hv = ld_vol_f2(&ghp[s * (H_DIM / 2) + tid]);
        sh[2 * tid]     = hv.x;
        sh[2 * tid + 1] = hv.y;
        if (tid < 16) sgin[s & 1][tid] = gin;
        __syncthreads();

        // 4. 16-lane dot product (conflict-free float4 smem reads)
        const float4* sh4 = (const float4*)sh;
        float acc = 0.f;
        #pragma unroll
        for (int m = 0; m < 8; m++) {
            float4 h4 = sh4[lane16 + m * 16];
            acc += wc[m].x * h4.x + wc[m].y * h4.y + wc[m].z * h4.z + wc[m].w * h4.w;
        }
        #pragma unroll
        for (int off = 8; off; off >>= 1)
            acc += __shfl_down_sync(0xffffffffu, acc, off, 16);
        if (lane16 == 0) ssum[rid] = acc;
        __syncthreads();

        // 5. Elementwise LSTM update for the 4 owned units; publish h[s+1]
        if (tid < 4) {
            const float* sg = sgin[s & 1];
            float iv = sigmoidf_(sg[0 * 4 + tid] + ssum[0 * 4 + tid]);
            float fv = sigmoidf_(sg[1 * 4 + tid] + ssum[1 * 4 + tid]);
            float gv = tanhf    (sg[2 * 4 + tid] + ssum[2 * 4 + tid]);
            float ov = sigmoidf_(sg[3 * 4 + tid] + ssum[3 * 4 + tid]);
            cval = fv * cval + iv * gv;
            hval = ov * tanhf(cval);
            st_vol_f(&g_h[(s + 1) * H_DIM + base + tid], hval);   // the "flag"
        }
        #pragma unroll
        for (int m = 0; m < 8; m++) wc[m] = wn[m];
    }

    // Output layout: [out(1), h(512), c(512)] — only if harness sized it so
    if (tid < 4 && out_size >= 1 + 2 * H_DIM) {
        d_out[1 + base + tid]          = hval;
        d_out[1 + H_DIM + base + tid]  = cval;
    }
}

// ---------------------------------------------------------------------------
// Kernel 4: out = sigmoid(h_T . fc_w + fc_b)   (O = 1)
// ---------------------------------------------------------------------------
__global__ void out_kernel(const float* __restrict__ fc_w,
                           const float* __restrict__ fc_b,
                           float* __restrict__ d_out)
{
    __shared__ float red[16];
    int tid = threadIdx.x;   // 512 threads
    float v = g_h[T_STEPS * H_DIM + tid] * fc_w[tid];
    #pragma unroll
    for (int off = 16; off; off >>= 1) v += __shfl_down_sync(0xffffffffu, v, off);
    if ((tid & 31) == 0) red[tid >> 5] = v;
    __syncthreads();
    if (tid < 16) {
        v = red[tid];
        #pragma unroll
        for (int off = 8; off; off >>= 1) v += __shfl_down_sync(0xffffu, v, off, 16);
        if (tid == 0) d_out[0] = 1.f / (1.f + expf(-(v + fc_b[0])));
    }
}

// ---------------------------------------------------------------------------
// Launch. Input order: x, tags, h0, c0, emb, W_ih, W_hh, b_ih, b_hh, fc_w, fc_b.
// ---------------------------------------------------------------------------
extern "C" void kernel_launch(void* const* d_in, const int* in_sizes, int n_in,
                              void* d_out, int out_size)
{
    const int*   x32  = (const int*)  d_in[0];   // int32 OR int64 (device probe)
    const int*   tags = (const int*)  d_in[1];
    const float* h0   = (const float*)d_in[2];
    const float* c0   = (const float*)d_in[3];
    const float* emb  = (const float*)d_in[4];
    const float* W_ih = (const float*)d_in[5];
    const float* W_hh = (const float*)d_in[6];
    const float* b_ih = (const float*)d_in[7];
    const float* b_hh = (const float*)d_in[8];
    const float* fc_w = (const float*)d_in[9];
    const float* fc_b = (const float*)d_in[10];
    float* out = (float*)d_out;

    init_kernel<<<((T_STEPS + 1) * H_DIM + 511) / 512, 512>>>(h0);
    gates_kernel<<<N_EXP * (G_DIM / ROWS_PER_BLK), 256>>>(x32, tags, emb, W_ih, b_ih, b_hh);
    lstm_kernel<<<NCTA, 256>>>(tags, W_hh, c0, out, out_size);
    out_kernel<<<1, H_DIM>>>(fc_w, fc_b, out);
}